// round 7
// baseline (speedup 1.0000x reference)
#include <cuda_runtime.h>
#include <cstdint>

// Scratch: __device__ globals (no allocation allowed).
#define NMAX 1000000
__device__ int   g_deg[NMAX];   // starts 0; each execution returns it to 0
__device__ float g_dinv[NMAX];
__device__ float g_xd[NMAX];    // dinv * x
__device__ float g_a1[NMAX];    // raw layer-1 accumulator (seeded in prep)
__device__ float g_yd[NMAX];    // dinv * y
__device__ float g_a2[NMAX];    // raw layer-2 accumulator (seeded in node)

// Grid-barrier state (returns to steady state each call; phase wraps safely).
__device__ unsigned g_count;
__device__ volatile unsigned g_phase;

__device__ __forceinline__ float ldcg(const float* p) {
    float v;
    asm volatile("ld.global.cg.f32 %0, [%1];" : "=f"(v) : "l"(p));
    return v;
}
__device__ __forceinline__ int ldcg_i(const int* p) {
    int v;
    asm volatile("ld.global.cg.s32 %0, [%1];" : "=r"(v) : "l"(p));
    return v;
}

// All-resident grid barrier (grid sized so every block is co-resident).
__device__ __forceinline__ void gsync(unsigned nb) {
    __syncthreads();
    __threadfence();
    if (threadIdx.x == 0) {
        unsigned my = g_phase;
        if (atomicAdd(&g_count, 1u) == nb - 1u) {
            g_count = 0u;
            __threadfence();
            g_phase = my + 1u;
        } else {
            while (g_phase == my) __nanosleep(64);
        }
    }
    __syncthreads();
    __threadfence();
}

// Edge scatter phase: acc[dst] += val[src], 8 edges/thread, grid-stride.
__device__ __forceinline__ void edge_phase(const int* __restrict__ src,
                                           const int* __restrict__ dst,
                                           const float* __restrict__ val,
                                           float* __restrict__ acc,
                                           int E, int tid, int nthreads, bool v4ok) {
    if (v4ok) {
        int nv = E >> 3;
        for (int g = tid; g < nv; g += nthreads) {
            const int4* ps = (const int4*)(src + g * 8);
            const int4* pd = (const int4*)(dst + g * 8);
            int4 s0 = __ldcs(ps);
            int4 s1 = __ldcs(ps + 1);
            int4 d0 = __ldcs(pd);
            int4 d1 = __ldcs(pd + 1);
            float v0 = ldcg(&val[s0.x]);
            float v1 = ldcg(&val[s0.y]);
            float v2 = ldcg(&val[s0.z]);
            float v3 = ldcg(&val[s0.w]);
            float v4 = ldcg(&val[s1.x]);
            float v5 = ldcg(&val[s1.y]);
            float v6 = ldcg(&val[s1.z]);
            float v7 = ldcg(&val[s1.w]);
            atomicAdd(&acc[d0.x], v0); atomicAdd(&acc[d0.y], v1);
            atomicAdd(&acc[d0.z], v2); atomicAdd(&acc[d0.w], v3);
            atomicAdd(&acc[d1.x], v4); atomicAdd(&acc[d1.y], v5);
            atomicAdd(&acc[d1.z], v6); atomicAdd(&acc[d1.w], v7);
        }
        for (int j = (nv << 3) + tid; j < E; j += nthreads)
            atomicAdd(&acc[dst[j]], ldcg(&val[src[j]]));
    } else {
        for (int j = tid; j < E; j += nthreads)
            atomicAdd(&acc[dst[j]], ldcg(&val[src[j]]));
    }
}

__device__ __forceinline__ float mlp8(float s, const float* W1, const float* b1,
                                      const float* W2) {
    float acc = 0.0f;
#pragma unroll
    for (int k = 0; k < 8; k++) {
        float h = fmaf(s, __ldg(&W1[k]), __ldg(&b1[k]));
        h = fmaxf(h, 0.0f);
        acc = fmaf(h, __ldg(&W2[k]), acc);
    }
    return acc;
}

__global__ void __launch_bounds__(256)
k_fused(const float* __restrict__ x,
        const int* __restrict__ src, const int* __restrict__ dst,
        const float* __restrict__ W1, const float* __restrict__ b1,
        const float* __restrict__ W2, const float* __restrict__ b2,
        float* __restrict__ out, int n, int E) {
    const int nthreads = gridDim.x * blockDim.x;
    const int tid = blockIdx.x * blockDim.x + threadIdx.x;
    const unsigned nb = gridDim.x;
    const bool v4ok = ((E & 3) == 0) && ((((uintptr_t)src) & 15) == 0) &&
                      ((((uintptr_t)dst) & 15) == 0);

    // ---- Phase 0: deg[dst] += 1 -------------------------------------------
    if (v4ok) {
        int nv = E >> 3;
        for (int g = tid; g < nv; g += nthreads) {
            const int4* p = (const int4*)(dst + g * 8);
            int4 d0 = __ldcs(p);
            int4 d1 = __ldcs(p + 1);
            atomicAdd(&g_deg[d0.x], 1); atomicAdd(&g_deg[d0.y], 1);
            atomicAdd(&g_deg[d0.z], 1); atomicAdd(&g_deg[d0.w], 1);
            atomicAdd(&g_deg[d1.x], 1); atomicAdd(&g_deg[d1.y], 1);
            atomicAdd(&g_deg[d1.z], 1); atomicAdd(&g_deg[d1.w], 1);
        }
        for (int j = (nv << 3) + tid; j < E; j += nthreads)
            atomicAdd(&g_deg[dst[j]], 1);
    } else {
        for (int j = tid; j < E; j += nthreads) atomicAdd(&g_deg[dst[j]], 1);
    }
    gsync(nb);

    // ---- Phase 1: dinv = rsqrt(deg+1); xd = dinv*x; a1 = xd; deg = 0 ------
    for (int i = tid; i < n; i += nthreads) {
        int dg = ldcg_i(&g_deg[i]);              // L2 path: written by RED
        float di = rsqrtf((float)(dg + 1));
        g_dinv[i] = di;
        float xd = di * __ldcs(&x[i]);
        g_xd[i] = xd;
        g_a1[i] = xd;                             // self-loop seed
        g_deg[i] = 0;                             // restore for next call
    }
    gsync(nb);

    // ---- Phase 2: a1[dst] += xd[src] --------------------------------------
    edge_phase(src, dst, g_xd, g_a1, E, tid, nthreads, v4ok);
    gsync(nb);

    // ---- Phase 3: yd = dinv * MLP(dinv*a1); a2 = yd -----------------------
    for (int i = tid; i < n; i += nthreads) {
        float di = ldcg(&g_dinv[i]);
        float a  = ldcg(&g_a1[i]);               // L2 path: written by RED
        float yd = di * mlp8(di * a, W1, b1, W2);
        g_yd[i] = yd;
        g_a2[i] = yd;                             // self-loop seed
    }
    gsync(nb);

    // ---- Phase 4: a2[dst] += yd[src] --------------------------------------
    edge_phase(src, dst, g_yd, g_a2, E, tid, nthreads, v4ok);
    gsync(nb);

    // ---- Phase 5: out = dinv*a2 + b2 --------------------------------------
    float bb = __ldg(&b2[0]);
    for (int i = tid; i < n; i += nthreads) {
        out[i] = fmaf(ldcg(&g_dinv[i]), ldcg(&g_a2[i]), bb);
    }
}

extern "C" void kernel_launch(void* const* d_in, const int* in_sizes, int n_in,
                              void* d_out, int out_size) {
    const float* x  = (const float*)d_in[0];
    const int*   ei = (const int*)d_in[1];     // [2, E]
    const float* W1 = (const float*)d_in[2];
    const float* b1 = (const float*)d_in[3];
    const float* W2 = (const float*)d_in[4];
    const float* b2 = (const float*)d_in[5];
    float* out = (float*)d_out;

    int n = in_sizes[0];           // 1,000,000
    int E = in_sizes[1] / 2;       // 10,000,000
    const int* src = ei;
    const int* dst = ei + E;

    const int T = 256;

    // Size grid so every block is co-resident (barrier-safe). Pure host
    // queries: no allocation, no sync, no stream ops — capture-safe.
    int dev = 0;
    cudaGetDevice(&dev);
    int nsm = 0;
    cudaDeviceGetAttribute(&nsm, cudaDevAttrMultiProcessorCount, dev);
    int occ = 0;
    cudaOccupancyMaxActiveBlocksPerMultiprocessor(&occ, k_fused, T, 0);
    if (nsm <= 0) nsm = 148;
    if (occ <= 0) occ = 1;
    int grid = nsm * occ;

    k_fused<<<grid, T>>>(x, src, dst, W1, b1, W2, b2, out, n, E);
}

// round 8
// speedup vs baseline: 1.3291x; 1.3291x over previous
#include <cuda_runtime.h>
#include <cstdint>

// Scratch: __device__ globals (no allocation allowed).
#define NMAX 1000000
__device__ int   g_deg[NMAX];   // starts 0; each execution returns it to 0
__device__ float g_dinv[NMAX];
__device__ float g_xd[NMAX];    // dinv * x
__device__ float g_a1[NMAX];    // raw layer-1 accumulator (seeded with xd)
__device__ float g_yd[NMAX];    // dinv * y

// ---------------------------------------------------------------------------
// Pass 1: count incoming edges at dst (deg starts at 0; self-loop via +1 later)
__global__ void __launch_bounds__(256) k_deg_v4(const int* __restrict__ dst, int E) {
    int i = blockIdx.x * blockDim.x + threadIdx.x;
    int base = i * 4;
    if (base + 3 < E) {
        int4 d = __ldcs((const int4*)(dst + base));
        atomicAdd(&g_deg[d.x], 1);
        atomicAdd(&g_deg[d.y], 1);
        atomicAdd(&g_deg[d.z], 1);
        atomicAdd(&g_deg[d.w], 1);
    } else {
        for (int j = base; j < E; j++) atomicAdd(&g_deg[dst[j]], 1);
    }
}
__global__ void k_deg_s(const int* __restrict__ dst, int E) {
    int i = blockIdx.x * blockDim.x + threadIdx.x;
    if (i < E) atomicAdd(&g_deg[dst[i]], 1);
}

// ---------------------------------------------------------------------------
// Pass 2: dinv = rsqrt(deg+1); xd = dinv*x; seed a1 = xd; reset deg = 0
__global__ void __launch_bounds__(256) k_prep_v4(const float* __restrict__ x, int n) {
    int i = blockIdx.x * blockDim.x + threadIdx.x;
    int base = i * 4;
    if (base + 3 < n) {
        int4   dg = *(const int4*)(g_deg + base);
        float4 xv = __ldcs((const float4*)(x + base));
        float4 di, xd;
        di.x = rsqrtf((float)(dg.x + 1)); di.y = rsqrtf((float)(dg.y + 1));
        di.z = rsqrtf((float)(dg.z + 1)); di.w = rsqrtf((float)(dg.w + 1));
        xd.x = di.x * xv.x; xd.y = di.y * xv.y; xd.z = di.z * xv.z; xd.w = di.w * xv.w;
        *(float4*)(g_dinv + base) = di;
        *(float4*)(g_xd  + base) = xd;
        *(float4*)(g_a1  + base) = xd;
        *(int4*)(g_deg + base) = make_int4(0, 0, 0, 0);
    } else {
        for (int j = base; j < n && j >= 0; j++) {
            float di = rsqrtf((float)(g_deg[j] + 1));
            g_dinv[j] = di;
            float xd = di * x[j];
            g_xd[j] = xd;
            g_a1[j] = xd;
            g_deg[j] = 0;
        }
    }
}

// ---------------------------------------------------------------------------
// Pass 3: a1[dst] += xd[src]   (4 edges/thread, fixed grid — proven config)
__global__ void __launch_bounds__(256) k_edge1_v4(const int* __restrict__ src,
                                                  const int* __restrict__ dst, int E) {
    int i = blockIdx.x * blockDim.x + threadIdx.x;
    int base = i * 4;
    if (base + 3 < E) {
        int4 s = __ldcs((const int4*)(src + base));
        int4 d = __ldcs((const int4*)(dst + base));
        float v0 = __ldg(&g_xd[s.x]);
        float v1 = __ldg(&g_xd[s.y]);
        float v2 = __ldg(&g_xd[s.z]);
        float v3 = __ldg(&g_xd[s.w]);
        atomicAdd(&g_a1[d.x], v0);
        atomicAdd(&g_a1[d.y], v1);
        atomicAdd(&g_a1[d.z], v2);
        atomicAdd(&g_a1[d.w], v3);
    } else {
        for (int j = base; j < E; j++)
            atomicAdd(&g_a1[dst[j]], __ldg(&g_xd[src[j]]));
    }
}
__global__ void k_edge1_s(const int* __restrict__ src, const int* __restrict__ dst, int E) {
    int i = blockIdx.x * blockDim.x + threadIdx.x;
    if (i < E) atomicAdd(&g_a1[dst[i]], __ldg(&g_xd[src[i]]));
}

// ---------------------------------------------------------------------------
// Pass 4: yd = dinv * MLP(dinv*a1); seed out = yd (self-loop term)
__device__ __forceinline__ float mlp8(float s, const float* W1, const float* b1,
                                      const float* W2) {
    float acc = 0.0f;
#pragma unroll
    for (int k = 0; k < 8; k++) {
        float h = fmaf(s, __ldg(&W1[k]), __ldg(&b1[k]));
        h = fmaxf(h, 0.0f);
        acc = fmaf(h, __ldg(&W2[k]), acc);
    }
    return acc;
}

__global__ void __launch_bounds__(256) k_node_v4(const float* __restrict__ W1,
                                                 const float* __restrict__ b1,
                                                 const float* __restrict__ W2,
                                                 float* __restrict__ out, int n) {
    int i = blockIdx.x * blockDim.x + threadIdx.x;
    int base = i * 4;
    if (base + 3 < n) {
        float4 di = *(const float4*)(g_dinv + base);
        float4 a  = *(const float4*)(g_a1 + base);
        float4 yd;
        yd.x = di.x * mlp8(di.x * a.x, W1, b1, W2);
        yd.y = di.y * mlp8(di.y * a.y, W1, b1, W2);
        yd.z = di.z * mlp8(di.z * a.z, W1, b1, W2);
        yd.w = di.w * mlp8(di.w * a.w, W1, b1, W2);
        *(float4*)(g_yd + base) = yd;
        *(float4*)(out + base) = yd;     // seed layer-2 accumulator in d_out
    } else {
        for (int j = base; j < n && j >= 0; j++) {
            float di = g_dinv[j];
            float yd = di * mlp8(di * g_a1[j], W1, b1, W2);
            g_yd[j] = yd;
            out[j] = yd;
        }
    }
}

// ---------------------------------------------------------------------------
// Pass 5: out[dst] += yd[src]  (accumulate directly into d_out)
__global__ void __launch_bounds__(256) k_edge2_v4(const int* __restrict__ src,
                                                  const int* __restrict__ dst,
                                                  float* __restrict__ out, int E) {
    int i = blockIdx.x * blockDim.x + threadIdx.x;
    int base = i * 4;
    if (base + 3 < E) {
        int4 s = __ldcs((const int4*)(src + base));
        int4 d = __ldcs((const int4*)(dst + base));
        float v0 = __ldg(&g_yd[s.x]);
        float v1 = __ldg(&g_yd[s.y]);
        float v2 = __ldg(&g_yd[s.z]);
        float v3 = __ldg(&g_yd[s.w]);
        atomicAdd(&out[d.x], v0);
        atomicAdd(&out[d.y], v1);
        atomicAdd(&out[d.z], v2);
        atomicAdd(&out[d.w], v3);
    } else {
        for (int j = base; j < E; j++)
            atomicAdd(&out[dst[j]], __ldg(&g_yd[src[j]]));
    }
}
__global__ void k_edge2_s(const int* __restrict__ src, const int* __restrict__ dst,
                          float* __restrict__ out, int E) {
    int i = blockIdx.x * blockDim.x + threadIdx.x;
    if (i < E) atomicAdd(&out[dst[i]], __ldg(&g_yd[src[i]]));
}

// ---------------------------------------------------------------------------
// Pass 6: out = dinv*out + b2  (in place)
__global__ void __launch_bounds__(256) k_final_v4(const float* __restrict__ b2,
                                                  float* __restrict__ out, int n) {
    int i = blockIdx.x * blockDim.x + threadIdx.x;
    int base = i * 4;
    float bb = __ldg(&b2[0]);
    if (base + 3 < n) {
        float4 di = *(const float4*)(g_dinv + base);
        float4 a  = *(const float4*)(out + base);
        float4 o;
        o.x = fmaf(di.x, a.x, bb);
        o.y = fmaf(di.y, a.y, bb);
        o.z = fmaf(di.z, a.z, bb);
        o.w = fmaf(di.w, a.w, bb);
        *(float4*)(out + base) = o;
    } else {
        for (int j = base; j < n && j >= 0; j++) out[j] = fmaf(g_dinv[j], out[j], bb);
    }
}

extern "C" void kernel_launch(void* const* d_in, const int* in_sizes, int n_in,
                              void* d_out, int out_size) {
    const float* x  = (const float*)d_in[0];
    const int*   ei = (const int*)d_in[1];     // [2, E]
    const float* W1 = (const float*)d_in[2];
    const float* b1 = (const float*)d_in[3];
    const float* W2 = (const float*)d_in[4];
    const float* b2 = (const float*)d_in[5];
    float* out = (float*)d_out;

    int n = in_sizes[0];           // 1,000,000
    int E = in_sizes[1] / 2;       // 10,000,000
    const int* src = ei;
    const int* dst = ei + E;

    const int T = 256;
    int gn4 = ((n + 3) / 4 + T - 1) / T;
    int gE4 = ((E + 3) / 4 + T - 1) / T;
    int gE  = (E + T - 1) / T;

    bool v4ok = ((E & 3) == 0) && ((((uintptr_t)ei) & 15) == 0);

    if (v4ok) {
        k_deg_v4  <<<gE4, T>>>(dst, E);
        k_prep_v4 <<<gn4, T>>>(x, n);
        k_edge1_v4<<<gE4, T>>>(src, dst, E);
        k_node_v4 <<<gn4, T>>>(W1, b1, W2, out, n);
        k_edge2_v4<<<gE4, T>>>(src, dst, out, E);
        k_final_v4<<<gn4, T>>>(b2, out, n);
    } else {
        k_deg_s   <<<gE, T>>>(dst, E);
        k_prep_v4 <<<gn4, T>>>(x, n);
        k_edge1_s <<<gE, T>>>(src, dst, E);
        k_node_v4 <<<gn4, T>>>(W1, b1, W2, out, n);
        k_edge2_s <<<gE, T>>>(src, dst, out, E);
        k_final_v4<<<gn4, T>>>(b2, out, n);
    }
}

// round 12
// speedup vs baseline: 1.3450x; 1.0120x over previous
#include <cuda_runtime.h>
#include <cstdint>

// Scratch: __device__ globals (no allocation allowed).
#define NMAX 1000000
__device__ int   g_deg[NMAX];   // starts 0; each execution returns it to 0
__device__ float g_dinv[NMAX];
__device__ float g_xd[NMAX];    // dinv * x
__device__ float g_a1[NMAX];    // raw layer-1 accumulator (seeded with xd)
__device__ float g_yd[NMAX];    // dinv * y

#if defined(__CUDA_ARCH__) && (__CUDA_ARCH__ >= 900)
#define GDEP_SYNC()  cudaGridDependencySynchronize()
#define GDEP_TRIG()  cudaTriggerProgrammaticLaunchCompletion()
#else
#define GDEP_SYNC()
#define GDEP_TRIG()
#endif

// ---------------------------------------------------------------------------
// Pass 1: deg[dst] += 1.  Indices are pure inputs -> no sync needed before them.
__global__ void __launch_bounds__(256) k_deg_v4(const int* __restrict__ dst, int E) {
    int i = blockIdx.x * blockDim.x + threadIdx.x;
    int base = i * 4;
    if (base + 3 < E) {
        int4 d = __ldcs((const int4*)(dst + base));
        atomicAdd(&g_deg[d.x], 1);
        atomicAdd(&g_deg[d.y], 1);
        atomicAdd(&g_deg[d.z], 1);
        atomicAdd(&g_deg[d.w], 1);
    } else {
        for (int j = base; j < E; j++) atomicAdd(&g_deg[dst[j]], 1);
    }
    GDEP_TRIG();
}

// ---------------------------------------------------------------------------
// Pass 2: dinv = rsqrt(deg+1); xd = dinv*x; seed a1 = xd; reset deg = 0
// Prefetch x (pure input) before syncing on k_deg's output.
__global__ void __launch_bounds__(256) k_prep_v4(const float* __restrict__ x, int n) {
    int i = blockIdx.x * blockDim.x + threadIdx.x;
    int base = i * 4;
    if (base + 3 < n) {
        float4 xv = __ldcs((const float4*)(x + base));   // independent prefetch
        GDEP_SYNC();
        int4 dg = *(const int4*)(g_deg + base);
        float4 di, xd;
        di.x = rsqrtf((float)(dg.x + 1)); di.y = rsqrtf((float)(dg.y + 1));
        di.z = rsqrtf((float)(dg.z + 1)); di.w = rsqrtf((float)(dg.w + 1));
        xd.x = di.x * xv.x; xd.y = di.y * xv.y; xd.z = di.z * xv.z; xd.w = di.w * xv.w;
        *(float4*)(g_dinv + base) = di;
        *(float4*)(g_xd  + base) = xd;
        *(float4*)(g_a1  + base) = xd;
        *(int4*)(g_deg + base) = make_int4(0, 0, 0, 0);
    } else {
        GDEP_SYNC();
        for (int j = base; j < n && j >= 0; j++) {
            float di = rsqrtf((float)(g_deg[j] + 1));
            g_dinv[j] = di;
            float xd = di * x[j];
            g_xd[j] = xd;
            g_a1[j] = xd;
            g_deg[j] = 0;
        }
    }
    GDEP_TRIG();
}

// ---------------------------------------------------------------------------
// Pass 3: a1[dst] += xd[src].  Prefetch indices, then sync before gathers.
__global__ void __launch_bounds__(256) k_edge1_v4(const int* __restrict__ src,
                                                  const int* __restrict__ dst, int E) {
    int i = blockIdx.x * blockDim.x + threadIdx.x;
    int base = i * 4;
    if (base + 3 < E) {
        int4 s = __ldcs((const int4*)(src + base));      // independent prefetch
        int4 d = __ldcs((const int4*)(dst + base));
        GDEP_SYNC();
        float v0 = __ldg(&g_xd[s.x]);
        float v1 = __ldg(&g_xd[s.y]);
        float v2 = __ldg(&g_xd[s.z]);
        float v3 = __ldg(&g_xd[s.w]);
        atomicAdd(&g_a1[d.x], v0);
        atomicAdd(&g_a1[d.y], v1);
        atomicAdd(&g_a1[d.z], v2);
        atomicAdd(&g_a1[d.w], v3);
    } else {
        GDEP_SYNC();
        for (int j = base; j < E; j++)
            atomicAdd(&g_a1[dst[j]], __ldg(&g_xd[src[j]]));
    }
    GDEP_TRIG();
}

// ---------------------------------------------------------------------------
// Pass 4: yd = dinv * MLP(dinv*a1); seed out = yd (self-loop term)
__device__ __forceinline__ float mlp8(float s, const float* W1, const float* b1,
                                      const float* W2) {
    float acc = 0.0f;
#pragma unroll
    for (int k = 0; k < 8; k++) {
        float h = fmaf(s, __ldg(&W1[k]), __ldg(&b1[k]));
        h = fmaxf(h, 0.0f);
        acc = fmaf(h, __ldg(&W2[k]), acc);
    }
    return acc;
}

__global__ void __launch_bounds__(256) k_node_v4(const float* __restrict__ W1,
                                                 const float* __restrict__ b1,
                                                 const float* __restrict__ W2,
                                                 float* __restrict__ out, int n) {
    GDEP_SYNC();                        // a1 produced by k_edge1
    int i = blockIdx.x * blockDim.x + threadIdx.x;
    int base = i * 4;
    if (base + 3 < n) {
        float4 di = *(const float4*)(g_dinv + base);
        float4 a  = *(const float4*)(g_a1 + base);
        float4 yd;
        yd.x = di.x * mlp8(di.x * a.x, W1, b1, W2);
        yd.y = di.y * mlp8(di.y * a.y, W1, b1, W2);
        yd.z = di.z * mlp8(di.z * a.z, W1, b1, W2);
        yd.w = di.w * mlp8(di.w * a.w, W1, b1, W2);
        *(float4*)(g_yd + base) = yd;
        *(float4*)(out + base) = yd;    // seed layer-2 accumulator in d_out
    } else {
        for (int j = base; j < n && j >= 0; j++) {
            float di = g_dinv[j];
            float yd = di * mlp8(di * g_a1[j], W1, b1, W2);
            g_yd[j] = yd;
            out[j] = yd;
        }
    }
    GDEP_TRIG();
}

// ---------------------------------------------------------------------------
// Pass 5: out[dst] += yd[src]
__global__ void __launch_bounds__(256) k_edge2_v4(const int* __restrict__ src,
                                                  const int* __restrict__ dst,
                                                  float* __restrict__ out, int E) {
    int i = blockIdx.x * blockDim.x + threadIdx.x;
    int base = i * 4;
    if (base + 3 < E) {
        int4 s = __ldcs((const int4*)(src + base));      // independent prefetch
        int4 d = __ldcs((const int4*)(dst + base));
        GDEP_SYNC();
        float v0 = __ldg(&g_yd[s.x]);
        float v1 = __ldg(&g_yd[s.y]);
        float v2 = __ldg(&g_yd[s.z]);
        float v3 = __ldg(&g_yd[s.w]);
        atomicAdd(&out[d.x], v0);
        atomicAdd(&out[d.y], v1);
        atomicAdd(&out[d.z], v2);
        atomicAdd(&out[d.w], v3);
    } else {
        GDEP_SYNC();
        for (int j = base; j < E; j++)
            atomicAdd(&out[dst[j]], __ldg(&g_yd[src[j]]));
    }
    GDEP_TRIG();
}

// ---------------------------------------------------------------------------
// Pass 6: out = dinv*out + b2  (in place)
__global__ void __launch_bounds__(256) k_final_v4(const float* __restrict__ b2,
                                                  float* __restrict__ out, int n) {
    GDEP_SYNC();
    int i = blockIdx.x * blockDim.x + threadIdx.x;
    int base = i * 4;
    float bb = __ldg(&b2[0]);
    if (base + 3 < n) {
        float4 di = *(const float4*)(g_dinv + base);
        float4 a  = *(const float4*)(out + base);
        float4 o;
        o.x = fmaf(di.x, a.x, bb);
        o.y = fmaf(di.y, a.y, bb);
        o.z = fmaf(di.z, a.z, bb);
        o.w = fmaf(di.w, a.w, bb);
        *(float4*)(out + base) = o;
    } else {
        for (int j = base; j < n && j >= 0; j++) out[j] = fmaf(g_dinv[j], out[j], bb);
    }
}

// Scalar fallbacks (unaligned edge buffer) — plain launches, no PDL.
__global__ void k_deg_s(const int* __restrict__ dst, int E) {
    int i = blockIdx.x * blockDim.x + threadIdx.x;
    if (i < E) atomicAdd(&g_deg[dst[i]], 1);
}
__global__ void k_edge1_s(const int* __restrict__ src, const int* __restrict__ dst, int E) {
    int i = blockIdx.x * blockDim.x + threadIdx.x;
    if (i < E) atomicAdd(&g_a1[dst[i]], __ldg(&g_xd[src[i]]));
}
__global__ void k_edge2_s(const int* __restrict__ src, const int* __restrict__ dst,
                          float* __restrict__ out, int E) {
    int i = blockIdx.x * blockDim.x + threadIdx.x;
    if (i < E) atomicAdd(&out[dst[i]], __ldg(&g_yd[src[i]]));
}

// ---------------------------------------------------------------------------
template <typename... Args>
static inline void launch_pdl(void (*kern)(Args...), dim3 grid, dim3 block,
                              bool pdl, Args... args) {
    cudaLaunchConfig_t cfg = {};
    cfg.gridDim = grid;
    cfg.blockDim = block;
    cfg.dynamicSmemBytes = 0;
    cfg.stream = 0;
    cudaLaunchAttribute attr[1];
    if (pdl) {
        attr[0].id = cudaLaunchAttributeProgrammaticStreamSerialization;
        attr[0].val.programmaticStreamSerializationAllowed = 1;
        cfg.attrs = attr;
        cfg.numAttrs = 1;
    }
    cudaLaunchKernelEx(&cfg, kern, args...);
}

extern "C" void kernel_launch(void* const* d_in, const int* in_sizes, int n_in,
                              void* d_out, int out_size) {
    const float* x  = (const float*)d_in[0];
    const int*   ei = (const int*)d_in[1];     // [2, E]
    const float* W1 = (const float*)d_in[2];
    const float* b1 = (const float*)d_in[3];
    const float* W2 = (const float*)d_in[4];
    const float* b2 = (const float*)d_in[5];
    float* out = (float*)d_out;

    int n = in_sizes[0];           // 1,000,000
    int E = in_sizes[1] / 2;       // 10,000,000
    const int* src = ei;
    const int* dst = ei + E;

    const int T = 256;
    int gn4 = ((n + 3) / 4 + T - 1) / T;
    int gE4 = ((E + 3) / 4 + T - 1) / T;
    int gE  = (E + T - 1) / T;

    bool v4ok = ((E & 3) == 0) && ((((uintptr_t)ei) & 15) == 0);

    if (v4ok) {
        // First kernel: plain launch. All successors: PDL (prefetch inputs,
        // gridDependencySynchronize before dependent data).
        launch_pdl(k_deg_v4,   dim3(gE4), dim3(T), false, dst, E);
        launch_pdl(k_prep_v4,  dim3(gn4), dim3(T), true,  x, n);
        launch_pdl(k_edge1_v4, dim3(gE4), dim3(T), true,  src, dst, E);
        launch_pdl(k_node_v4,  dim3(gn4), dim3(T), true,  W1, b1, W2, out, n);
        launch_pdl(k_edge2_v4, dim3(gE4), dim3(T), true,  src, dst, out, E);
        launch_pdl(k_final_v4, dim3(gn4), dim3(T), true,  b2, out, n);
    } else {
        k_deg_s   <<<gE, T>>>(dst, E);
        k_prep_v4 <<<gn4, T>>>(x, n);       // GDEP_SYNC is a no-op extra here
        k_edge1_s <<<gE, T>>>(src, dst, E);
        k_node_v4 <<<gn4, T>>>(W1, b1, W2, out, n);
        k_edge2_s <<<gE, T>>>(src, dst, out, E);
        k_final_v4<<<gn4, T>>>(b2, out, n);
    }
}